// round 1
// baseline (speedup 1.0000x reference)
#include <cuda_runtime.h>
#include <cstdint>

#define BB 8
#define LL 2048
#define HH 256
#define M_TOT (BB*LL)

// Scratch (static device globals — allocation-free, graph-capture legal)
__device__ float g_Q[M_TOT*HH];
__device__ float g_K[M_TOT*HH];
__device__ float g_V[M_TOT*HH];

// ---------------------------------------------------------------------------
// TF32 helpers
// ---------------------------------------------------------------------------
__device__ __forceinline__ uint32_t f2tf32(float f) {
    uint32_t u;
    asm("cvt.rna.tf32.f32 %0, %1;" : "=r"(u) : "f"(f));
    return u;
}
__device__ __forceinline__ void split_tf32(float f, uint32_t& hi, uint32_t& lo) {
    uint32_t h;
    asm("cvt.rna.tf32.f32 %0, %1;" : "=r"(h) : "f"(f));
    float r = f - __uint_as_float(h);
    asm("cvt.rna.tf32.f32 %0, %1;" : "=r"(lo) : "f"(r));
    hi = h;
}
__device__ __forceinline__ void mma_tf32(float c[4], const uint32_t a[4], const uint32_t b[2]) {
    asm volatile(
        "mma.sync.aligned.m16n8k8.row.col.f32.tf32.tf32.f32 "
        "{%0,%1,%2,%3}, {%4,%5,%6,%7}, {%8,%9}, {%0,%1,%2,%3};"
        : "+f"(c[0]), "+f"(c[1]), "+f"(c[2]), "+f"(c[3])
        : "r"(a[0]), "r"(a[1]), "r"(a[2]), "r"(a[3]), "r"(b[0]), "r"(b[1]));
}

// ---------------------------------------------------------------------------
// Kernel 1: QKV projection, y = x @ W^T, 3xTF32 compensated (near-fp32 accuracy)
// grid (M_TOT/64, HH/64, 3), block 256 (8 warps, 4m x 2n of a 64x64 tile)
// Output is rounded to TF32 at store so the attention mma can consume raw bits.
// ---------------------------------------------------------------------------
__global__ __launch_bounds__(256, 1)
void proj_kernel(const float* __restrict__ x,
                 const float* __restrict__ Wq,
                 const float* __restrict__ Wk,
                 const float* __restrict__ Wv,
                 const int* __restrict__ lens)
{
    const int mtile = blockIdx.x, ntile = blockIdx.y, which = blockIdx.z;
    const float* Wp = (which == 0) ? Wq : (which == 1) ? Wk : Wv;
    float* outp     = (which == 0) ? g_Q : (which == 1) ? g_K : g_V;

    // K/V rows beyond len[b] are never read by attention — skip those tiles.
    if (which != 0) {
        int m0 = mtile * 64;
        int b = m0 / LL, pos = m0 % LL;
        if (pos >= lens[b]) return;
    }

    __shared__ float Xs[64][68];   // pad 4: bank = (4r+c)%32, conflict-free frags
    __shared__ float Ws[64][68];

    const int tid = threadIdx.x;
    const int lane = tid & 31, warp = tid >> 5;
    const int wm = warp & 3, wn = warp >> 2;   // 4 x 2 warp grid

    float acc[4][4];
    #pragma unroll
    for (int i = 0; i < 4; i++)
        #pragma unroll
        for (int j = 0; j < 4; j++) acc[i][j] = 0.f;

    for (int kc = 0; kc < HH; kc += 64) {
        #pragma unroll
        for (int it = 0; it < 4; it++) {
            int idx = tid + it * 256;          // 1024 float4 per tile
            int r = idx >> 4, c4 = (idx & 15) * 4;
            *(float4*)&Xs[r][c4] = *(const float4*)&x[(size_t)(mtile * 64 + r) * HH + kc + c4];
            *(float4*)&Ws[r][c4] = *(const float4*)&Wp[(size_t)(ntile * 64 + r) * HH + kc + c4];
        }
        __syncthreads();

        #pragma unroll
        for (int ks = 0; ks < 64; ks += 8) {
            const int ar = wm * 16 + (lane >> 2);
            const int ac = ks + (lane & 3);
            uint32_t ah[4], al[4];
            split_tf32(Xs[ar][ac],       ah[0], al[0]);
            split_tf32(Xs[ar + 8][ac],   ah[1], al[1]);
            split_tf32(Xs[ar][ac + 4],   ah[2], al[2]);
            split_tf32(Xs[ar + 8][ac + 4], ah[3], al[3]);
            #pragma unroll
            for (int nf = 0; nf < 4; nf++) {
                int br = wn * 32 + nf * 8 + (lane >> 2);   // n index (W row)
                uint32_t bh[2], bl[2];
                split_tf32(Ws[br][ac],     bh[0], bl[0]);
                split_tf32(Ws[br][ac + 4], bh[1], bl[1]);
                mma_tf32(acc[nf], al, bh);   // small terms first
                mma_tf32(acc[nf], ah, bl);
                mma_tf32(acc[nf], ah, bh);
            }
        }
        __syncthreads();
    }

    // Store rounded-to-TF32 (attention consumes raw bits, no cvt needed there)
    const int r0 = mtile * 64 + wm * 16 + (lane >> 2);
    #pragma unroll
    for (int nf = 0; nf < 4; nf++) {
        int c0 = ntile * 64 + wn * 32 + nf * 8 + 2 * (lane & 3);
        outp[(size_t)r0 * HH + c0]           = __uint_as_float(f2tf32(acc[nf][0]));
        outp[(size_t)r0 * HH + c0 + 1]       = __uint_as_float(f2tf32(acc[nf][1]));
        outp[(size_t)(r0 + 8) * HH + c0]     = __uint_as_float(f2tf32(acc[nf][2]));
        outp[(size_t)(r0 + 8) * HH + c0 + 1] = __uint_as_float(f2tf32(acc[nf][3]));
    }
}

// ---------------------------------------------------------------------------
// Kernel 2: flash attention. grid (LL/64, BB), block 256, dynamic smem.
// Q tile (64x256) resident; loop K/V tiles of 64 rows up to ceil(len/64).
// Online softmax (m, l, alpha) per row; O accumulators in registers.
// ---------------------------------------------------------------------------
#define QS_STRIDE 260   // bank = (4r+c)%32 for frag patterns -> conflict-free
#define VS_STRIDE 264   // bank = (8k+d)%32 for PV B-frags    -> conflict-free
#define SS_STRIDE 68

#define SMEM_FLOATS (64*QS_STRIDE /*Q*/ + 64*QS_STRIDE /*K*/ + 64*VS_STRIDE /*V*/ \
                     + 64*SS_STRIDE /*S*/ + 192 /*m,l,alpha*/)
#define ATTN_SMEM_BYTES (SMEM_FLOATS * 4)

__global__ __launch_bounds__(256, 1)
void attn_kernel(const int* __restrict__ lens, float* __restrict__ out)
{
    extern __shared__ float sm[];
    float* Qs   = sm;
    float* Ks   = Qs + 64 * QS_STRIDE;
    float* Vs   = Ks + 64 * QS_STRIDE;
    float* Ss   = Vs + 64 * VS_STRIDE;
    float* rowm = Ss + 64 * SS_STRIDE;
    float* rowl = rowm + 64;
    float* rowa = rowl + 64;

    const int qt = blockIdx.x, b = blockIdx.y;
    const int len = lens[b];
    const int tid = threadIdx.x, lane = tid & 31, warp = tid >> 5;
    const int wm = warp & 3, wn = warp >> 2;
    const size_t base = (size_t)b * LL * HH;

    // Load Q tile (64 x 256)
    #pragma unroll
    for (int it = 0; it < 16; it++) {
        int idx = tid + it * 256;              // 4096 float4
        int r = idx >> 6, c4 = (idx & 63) * 4;
        *(float4*)&Qs[r * QS_STRIDE + c4] =
            *(const float4*)&g_Q[base + (size_t)(qt * 64 + r) * HH + c4];
    }
    if (tid < 64) { rowm[tid] = -1e30f; rowl[tid] = 0.f; }

    // O accumulators: warp owns rows [wm*16,+16), cols [wn*128,+128) -> 16 n-frags
    float o[16][4];
    #pragma unroll
    for (int i = 0; i < 16; i++)
        #pragma unroll
        for (int j = 0; j < 4; j++) o[i][j] = 0.f;

    __syncthreads();

    const int nkt = (len + 63) >> 6;
    for (int kt = 0; kt < nkt; kt++) {
        // Load K and V tiles
        #pragma unroll
        for (int it = 0; it < 16; it++) {
            int idx = tid + it * 256;
            int r = idx >> 6, c4 = (idx & 63) * 4;
            size_t g = base + (size_t)(kt * 64 + r) * HH + c4;
            *(float4*)&Ks[r * QS_STRIDE + c4] = *(const float4*)&g_K[g];
            *(float4*)&Vs[r * VS_STRIDE + c4] = *(const float4*)&g_V[g];
        }
        __syncthreads();

        // S = Q K^T : warp region rows [wm*16,+16), cols [wn*32,+32), K-dim 256
        float s[4][4];
        #pragma unroll
        for (int i = 0; i < 4; i++)
            #pragma unroll
            for (int j = 0; j < 4; j++) s[i][j] = 0.f;

        #pragma unroll
        for (int ks = 0; ks < HH; ks += 8) {
            const int ar = wm * 16 + (lane >> 2);
            const int ac = ks + (lane & 3);
            uint32_t a[4];   // raw bits: Q is pre-rounded to tf32
            a[0] = __float_as_uint(Qs[ar * QS_STRIDE + ac]);
            a[1] = __float_as_uint(Qs[(ar + 8) * QS_STRIDE + ac]);
            a[2] = __float_as_uint(Qs[ar * QS_STRIDE + ac + 4]);
            a[3] = __float_as_uint(Qs[(ar + 8) * QS_STRIDE + ac + 4]);
            #pragma unroll
            for (int nf = 0; nf < 4; nf++) {
                int br = wn * 32 + nf * 8 + (lane >> 2);
                uint32_t bb[2];
                bb[0] = __float_as_uint(Ks[br * QS_STRIDE + ac]);
                bb[1] = __float_as_uint(Ks[br * QS_STRIDE + ac + 4]);
                mma_tf32(s[nf], a, bb);
            }
        }

        // Scale + key-padding mask, write S to smem
        {
            const int r0 = wm * 16 + (lane >> 2);
            #pragma unroll
            for (int nf = 0; nf < 4; nf++) {
                int c0 = wn * 32 + nf * 8 + 2 * (lane & 3);
                int kg = kt * 64 + c0;
                float v0 = (kg     < len) ? s[nf][0] * 0.0625f : -1e30f;
                float v1 = (kg + 1 < len) ? s[nf][1] * 0.0625f : -1e30f;
                float v2 = (kg     < len) ? s[nf][2] * 0.0625f : -1e30f;
                float v3 = (kg + 1 < len) ? s[nf][3] * 0.0625f : -1e30f;
                Ss[r0 * SS_STRIDE + c0]           = v0;
                Ss[r0 * SS_STRIDE + c0 + 1]       = v1;
                Ss[(r0 + 8) * SS_STRIDE + c0]     = v2;
                Ss[(r0 + 8) * SS_STRIDE + c0 + 1] = v3;
            }
        }
        __syncthreads();

        // Online softmax: 4 threads per row, 16 cols each (row = tid/4 in-warp)
        {
            const int row = tid >> 2, part = tid & 3;
            float* srow = &Ss[row * SS_STRIDE + part * 16];
            float mx = -1e30f;
            #pragma unroll
            for (int i = 0; i < 16; i++) mx = fmaxf(mx, srow[i]);
            mx = fmaxf(mx, __shfl_xor_sync(0xffffffffu, mx, 1));
            mx = fmaxf(mx, __shfl_xor_sync(0xffffffffu, mx, 2));
            const float mold = rowm[row];
            const float mnew = fmaxf(mold, mx);
            float sum = 0.f;
            #pragma unroll
            for (int i = 0; i < 16; i++) {
                float p = __expf(srow[i] - mnew);
                srow[i] = p;                       // P overwrites S in place
                sum += p;
            }
            sum += __shfl_xor_sync(0xffffffffu, sum, 1);
            sum += __shfl_xor_sync(0xffffffffu, sum, 2);
            if (part == 0) {
                float alpha = __expf(mold - mnew);
                rowa[row] = alpha;
                rowl[row] = rowl[row] * alpha + sum;
                rowm[row] = mnew;
            }
        }
        __syncthreads();

        // Rescale O, accumulate O += P @ V  (warp: rows wm*16..+16, cols wn*128..+128)
        {
            const int r0 = wm * 16 + (lane >> 2);
            const float a0 = rowa[r0], a1 = rowa[r0 + 8];
            #pragma unroll
            for (int nf = 0; nf < 16; nf++) {
                o[nf][0] *= a0; o[nf][1] *= a0;
                o[nf][2] *= a1; o[nf][3] *= a1;
            }
            #pragma unroll
            for (int ks = 0; ks < 64; ks += 8) {
                const int ac = ks + (lane & 3);
                uint32_t a[4];                      // P fresh -> explicit round
                a[0] = f2tf32(Ss[r0 * SS_STRIDE + ac]);
                a[1] = f2tf32(Ss[(r0 + 8) * SS_STRIDE + ac]);
                a[2] = f2tf32(Ss[r0 * SS_STRIDE + ac + 4]);
                a[3] = f2tf32(Ss[(r0 + 8) * SS_STRIDE + ac + 4]);
                #pragma unroll
                for (int nf = 0; nf < 16; nf++) {
                    int bc = wn * 128 + nf * 8 + (lane >> 2);     // d column
                    uint32_t bb[2];                               // V pre-rounded
                    bb[0] = __float_as_uint(Vs[ac * VS_STRIDE + bc]);
                    bb[1] = __float_as_uint(Vs[(ac + 4) * VS_STRIDE + bc]);
                    mma_tf32(o[nf], a, bb);
                }
            }
        }
        __syncthreads();   // before next tile overwrites Ks/Vs/Ss
    }

    // Epilogue: O /= l, store
    {
        const int r0 = wm * 16 + (lane >> 2);
        const float inv0 = 1.f / rowl[r0];
        const float inv1 = 1.f / rowl[r0 + 8];
        const size_t orow0 = base + (size_t)(qt * 64 + r0) * HH;
        const size_t orow1 = base + (size_t)(qt * 64 + r0 + 8) * HH;
        #pragma unroll
        for (int nf = 0; nf < 16; nf++) {
            int c0 = wn * 128 + nf * 8 + 2 * (lane & 3);
            out[orow0 + c0]     = o[nf][0] * inv0;
            out[orow0 + c0 + 1] = o[nf][1] * inv0;
            out[orow1 + c0]     = o[nf][2] * inv1;
            out[orow1 + c0 + 1] = o[nf][3] * inv1;
        }
    }
}

// ---------------------------------------------------------------------------
// Launch
// ---------------------------------------------------------------------------
extern "C" void kernel_launch(void* const* d_in, const int* in_sizes, int n_in,
                              void* d_out, int out_size)
{
    const float* x    = (const float*)d_in[0];
    const float* Wq   = (const float*)d_in[1];
    const float* Wk   = (const float*)d_in[2];
    const float* Wv   = (const float*)d_in[3];
    const int*   lens = (const int*)d_in[4];
    float* out = (float*)d_out;
    (void)in_sizes; (void)n_in; (void)out_size;

    // Unconditional (no static guards); attribute set is not a stream op,
    // safe under graph capture.
    cudaFuncSetAttribute(attn_kernel,
                         cudaFuncAttributeMaxDynamicSharedMemorySize,
                         ATTN_SMEM_BYTES);

    dim3 pgrid(M_TOT / 64, HH / 64, 3);
    proj_kernel<<<pgrid, 256>>>(x, Wq, Wk, Wv, lens);

    dim3 agrid(LL / 64, BB);
    attn_kernel<<<agrid, 256, ATTN_SMEM_BYTES>>>(lens, out);
}

// round 3
// speedup vs baseline: 1.1853x; 1.1853x over previous
#include <cuda_runtime.h>
#include <cstdint>

#define BB 8
#define LL 2048
#define HH 256
#define M_TOT (BB*LL)

// Scratch (static device globals — allocation-free, graph-capture legal)
__device__ float g_Q[M_TOT*HH];
__device__ float g_K[M_TOT*HH];
__device__ float g_V[M_TOT*HH];

// ---------------------------------------------------------------------------
// Helpers
// ---------------------------------------------------------------------------
__device__ __forceinline__ uint32_t f2tf32(float f) {
    uint32_t u;
    asm("cvt.rna.tf32.f32 %0, %1;" : "=r"(u) : "f"(f));
    return u;
}
__device__ __forceinline__ void mma_tf32(float c[4], const uint32_t a[4], const uint32_t b[2]) {
    asm volatile(
        "mma.sync.aligned.m16n8k8.row.col.f32.tf32.tf32.f32 "
        "{%0,%1,%2,%3}, {%4,%5,%6,%7}, {%8,%9}, {%0,%1,%2,%3};"
        : "+f"(c[0]), "+f"(c[1]), "+f"(c[2]), "+f"(c[3])
        : "r"(a[0]), "r"(a[1]), "r"(a[2]), "r"(a[3]), "r"(b[0]), "r"(b[1]));
}
__device__ __forceinline__ void cp16(float* s, const float* g) {
    uint32_t sa = (uint32_t)__cvta_generic_to_shared(s);
    asm volatile("cp.async.cg.shared.global [%0], [%1], 16;" :: "r"(sa), "l"(g));
}
#define CP_COMMIT() asm volatile("cp.async.commit_group;" ::: "memory")
#define CP_WAIT1()  asm volatile("cp.async.wait_group 1;" ::: "memory")

// ---------------------------------------------------------------------------
// Kernel 1: QKV projection, y = x @ W^T, single-pass TF32.
// Operands are rounded to TF32 once at smem-copy time; inner loop = LDS + MMA.
// grid (M_TOT/64, HH/64, 3), block 256 (8 warps, 4m x 2n of a 64x64 tile).
// ---------------------------------------------------------------------------
__global__ __launch_bounds__(256, 2)
void proj_kernel(const float* __restrict__ x,
                 const float* __restrict__ Wq,
                 const float* __restrict__ Wk,
                 const float* __restrict__ Wv,
                 const int* __restrict__ lens)
{
    const int mtile = blockIdx.x, ntile = blockIdx.y, which = blockIdx.z;
    const float* Wp = (which == 0) ? Wq : (which == 1) ? Wk : Wv;
    float* outp     = (which == 0) ? g_Q : (which == 1) ? g_K : g_V;

    // K/V rows beyond len[b] are never read by attention — skip those tiles.
    if (which != 0) {
        int m0 = mtile * 64;
        int b = m0 / LL, pos = m0 % LL;
        if (pos >= lens[b]) return;
    }

    __shared__ float Xs[64][68];   // pad 4: bank = (4r+c)%32, conflict-free frags
    __shared__ float Ws[64][68];

    const int tid = threadIdx.x;
    const int lane = tid & 31, warp = tid >> 5;
    const int wm = warp & 3, wn = warp >> 2;   // 4 x 2 warp grid

    float acc[4][4];
    #pragma unroll
    for (int i = 0; i < 4; i++)
        #pragma unroll
        for (int j = 0; j < 4; j++) acc[i][j] = 0.f;

    for (int kc = 0; kc < HH; kc += 64) {
        #pragma unroll
        for (int it = 0; it < 4; it++) {
            int idx = tid + it * 256;          // 1024 float4 per tile
            int r = idx >> 4, c4 = (idx & 15) * 4;
            float4 xv = *(const float4*)&x[(size_t)(mtile * 64 + r) * HH + kc + c4];
            float4 wv = *(const float4*)&Wp[(size_t)(ntile * 64 + r) * HH + kc + c4];
            // round to tf32 once here; frags consume raw bits
            xv.x = __uint_as_float(f2tf32(xv.x)); xv.y = __uint_as_float(f2tf32(xv.y));
            xv.z = __uint_as_float(f2tf32(xv.z)); xv.w = __uint_as_float(f2tf32(xv.w));
            wv.x = __uint_as_float(f2tf32(wv.x)); wv.y = __uint_as_float(f2tf32(wv.y));
            wv.z = __uint_as_float(f2tf32(wv.z)); wv.w = __uint_as_float(f2tf32(wv.w));
            *(float4*)&Xs[r][c4] = xv;
            *(float4*)&Ws[r][c4] = wv;
        }
        __syncthreads();

        #pragma unroll
        for (int ks = 0; ks < 64; ks += 8) {
            const int ar = wm * 16 + (lane >> 2);
            const int ac = ks + (lane & 3);
            uint32_t a[4];
            a[0] = __float_as_uint(Xs[ar][ac]);
            a[1] = __float_as_uint(Xs[ar + 8][ac]);
            a[2] = __float_as_uint(Xs[ar][ac + 4]);
            a[3] = __float_as_uint(Xs[ar + 8][ac + 4]);
            #pragma unroll
            for (int nf = 0; nf < 4; nf++) {
                int br = wn * 32 + nf * 8 + (lane >> 2);   // n index (W row)
                uint32_t b[2];
                b[0] = __float_as_uint(Ws[br][ac]);
                b[1] = __float_as_uint(Ws[br][ac + 4]);
                mma_tf32(acc[nf], a, b);
            }
        }
        __syncthreads();
    }

    // Store rounded-to-TF32 (attention consumes raw bits, no cvt needed there)
    const int r0 = mtile * 64 + wm * 16 + (lane >> 2);
    #pragma unroll
    for (int nf = 0; nf < 4; nf++) {
        int c0 = ntile * 64 + wn * 32 + nf * 8 + 2 * (lane & 3);
        outp[(size_t)r0 * HH + c0]           = __uint_as_float(f2tf32(acc[nf][0]));
        outp[(size_t)r0 * HH + c0 + 1]       = __uint_as_float(f2tf32(acc[nf][1]));
        outp[(size_t)(r0 + 8) * HH + c0]     = __uint_as_float(f2tf32(acc[nf][2]));
        outp[(size_t)(r0 + 8) * HH + c0 + 1] = __uint_as_float(f2tf32(acc[nf][3]));
    }
}

// ---------------------------------------------------------------------------
// Kernel 2: flash attention. grid (LL/64, BB), block 512 (16 warps), dyn smem.
// Q tile (64x256) resident (pre-scaled by 1/sqrt(d)); K/V tiles single-buffer
// cp.async pipelined: K[t+1] lands during softmax+PV, V[t+1] during next S.
// Warp grid: 4m x 4n. S-phase: warp = 16 rows x 16 cols. PV: 16 rows x 64 d.
// ---------------------------------------------------------------------------
#define QS_STRIDE 260   // %32==4: bank 4r+c conflict-free for frag loads
#define VS_STRIDE 264   // %32==8: bank 8k+d conflict-free for PV B-frags
#define SS_STRIDE 68

#define SMEM_FLOATS (64*QS_STRIDE /*Q*/ + 64*QS_STRIDE /*K*/ + 64*VS_STRIDE /*V*/ \
                     + 64*SS_STRIDE /*S*/ + 192 /*m,l,alpha*/)
#define ATTN_SMEM_BYTES (SMEM_FLOATS * 4)

__global__ __launch_bounds__(512, 1)
void attn_kernel(const int* __restrict__ lens, float* __restrict__ out)
{
    extern __shared__ float sm[];
    float* Qs   = sm;
    float* Ks   = Qs + 64 * QS_STRIDE;
    float* Vs   = Ks + 64 * QS_STRIDE;
    float* Ss   = Vs + 64 * VS_STRIDE;
    float* rowm = Ss + 64 * SS_STRIDE;
    float* rowl = rowm + 64;
    float* rowa = rowl + 64;

    const int qt = blockIdx.x, b = blockIdx.y;
    const int len = lens[b];
    const int tid = threadIdx.x, lane = tid & 31, warp = tid >> 5;
    const int wm = warp & 3, wn = warp >> 2;        // 4 x 4 warp grid
    const size_t base = (size_t)b * LL * HH;
    const int nkt = (len + 63) >> 6;

    // Prologue: async-load K0 (group0) and V0 (group1)
    #pragma unroll
    for (int it = 0; it < 8; it++) {
        int idx = tid + it * 512;                  // 4096 float4
        int r = idx >> 6, c4 = (idx & 63) * 4;
        cp16(&Ks[r * QS_STRIDE + c4], &g_K[base + (size_t)r * HH + c4]);
    }
    CP_COMMIT();
    #pragma unroll
    for (int it = 0; it < 8; it++) {
        int idx = tid + it * 512;
        int r = idx >> 6, c4 = (idx & 63) * 4;
        cp16(&Vs[r * VS_STRIDE + c4], &g_V[base + (size_t)r * HH + c4]);
    }
    CP_COMMIT();

    // Q tile (64 x 256), pre-scaled by 1/sqrt(256) = 2^-4 (exact on tf32 bits)
    #pragma unroll
    for (int it = 0; it < 8; it++) {
        int idx = tid + it * 512;
        int r = idx >> 6, c4 = (idx & 63) * 4;
        float4 qv = *(const float4*)&g_Q[base + (size_t)(qt * 64 + r) * HH + c4];
        qv.x *= 0.0625f; qv.y *= 0.0625f; qv.z *= 0.0625f; qv.w *= 0.0625f;
        *(float4*)&Qs[r * QS_STRIDE + c4] = qv;
    }
    if (tid < 64) { rowm[tid] = -1e30f; rowl[tid] = 0.f; }

    // O accumulators: warp owns rows [wm*16,+16), cols [wn*64,+64) -> 8 n-frags
    float o[8][4];
    #pragma unroll
    for (int i = 0; i < 8; i++)
        #pragma unroll
        for (int j = 0; j < 4; j++) o[i][j] = 0.f;

    for (int kt = 0; kt < nkt; kt++) {
        CP_WAIT1();            // K[t] done (V[t] may still be in flight)
        __syncthreads();

        // ---- S = Q K^T : warp rows [wm*16,+16), cols [wn*16,+16), k-dim 256
        float s[2][4];
        #pragma unroll
        for (int i = 0; i < 2; i++)
            #pragma unroll
            for (int j = 0; j < 4; j++) s[i][j] = 0.f;

        #pragma unroll
        for (int ks = 0; ks < HH; ks += 8) {
            const int ar = wm * 16 + (lane >> 2);
            const int ac = ks + (lane & 3);
            uint32_t a[4];   // raw bits: Q pre-rounded tf32 (scaled)
            a[0] = __float_as_uint(Qs[ar * QS_STRIDE + ac]);
            a[1] = __float_as_uint(Qs[(ar + 8) * QS_STRIDE + ac]);
            a[2] = __float_as_uint(Qs[ar * QS_STRIDE + ac + 4]);
            a[3] = __float_as_uint(Qs[(ar + 8) * QS_STRIDE + ac + 4]);
            #pragma unroll
            for (int nf = 0; nf < 2; nf++) {
                int br = wn * 16 + nf * 8 + (lane >> 2);
                uint32_t bb[2];
                bb[0] = __float_as_uint(Ks[br * QS_STRIDE + ac]);
                bb[1] = __float_as_uint(Ks[br * QS_STRIDE + ac + 4]);
                mma_tf32(s[nf], a, bb);
            }
        }

        // ---- key-padding mask + write S tile to smem
        {
            const int r0 = wm * 16 + (lane >> 2);
            #pragma unroll
            for (int nf = 0; nf < 2; nf++) {
                int c0 = wn * 16 + nf * 8 + 2 * (lane & 3);
                int kg = kt * 64 + c0;
                float v0 = (kg     < len) ? s[nf][0] : -1e30f;
                float v1 = (kg + 1 < len) ? s[nf][1] : -1e30f;
                float v2 = (kg     < len) ? s[nf][2] : -1e30f;
                float v3 = (kg + 1 < len) ? s[nf][3] : -1e30f;
                Ss[r0 * SS_STRIDE + c0]           = v0;
                Ss[r0 * SS_STRIDE + c0 + 1]       = v1;
                Ss[(r0 + 8) * SS_STRIDE + c0]     = v2;
                Ss[(r0 + 8) * SS_STRIDE + c0 + 1] = v3;
            }
        }
        __syncthreads();   // S visible; all K reads done

        // ---- prefetch K[t+1] into the (now free) K buffer
        if (kt + 1 < nkt) {
            #pragma unroll
            for (int it = 0; it < 8; it++) {
                int idx = tid + it * 512;
                int r = idx >> 6, c4 = (idx & 63) * 4;
                cp16(&Ks[r * QS_STRIDE + c4],
                     &g_K[base + (size_t)((kt + 1) * 64 + r) * HH + c4]);
            }
        }
        CP_COMMIT();

        // ---- online softmax: 8 threads per row, 8 cols each
        {
            const int row = tid >> 3, part = tid & 7;
            float* srow = &Ss[row * SS_STRIDE + part * 8];
            float4 p0 = *(float4*)&srow[0];
            float4 p1 = *(float4*)&srow[4];
            float mx = fmaxf(fmaxf(fmaxf(p0.x, p0.y), fmaxf(p0.z, p0.w)),
                             fmaxf(fmaxf(p1.x, p1.y), fmaxf(p1.z, p1.w)));
            mx = fmaxf(mx, __shfl_xor_sync(0xffffffffu, mx, 1));
            mx = fmaxf(mx, __shfl_xor_sync(0xffffffffu, mx, 2));
            mx = fmaxf(mx, __shfl_xor_sync(0xffffffffu, mx, 4));
            const float mold = rowm[row];
            const float mnew = fmaxf(mold, mx);
            p0.x = __expf(p0.x - mnew); p0.y = __expf(p0.y - mnew);
            p0.z = __expf(p0.z - mnew); p0.w = __expf(p0.w - mnew);
            p1.x = __expf(p1.x - mnew); p1.y = __expf(p1.y - mnew);
            p1.z = __expf(p1.z - mnew); p1.w = __expf(p1.w - mnew);
            float sum = (p0.x + p0.y) + (p0.z + p0.w)
                      + (p1.x + p1.y) + (p1.z + p1.w);
            *(float4*)&srow[0] = p0;           // P overwrites S in place
            *(float4*)&srow[4] = p1;
            sum += __shfl_xor_sync(0xffffffffu, sum, 1);
            sum += __shfl_xor_sync(0xffffffffu, sum, 2);
            sum += __shfl_xor_sync(0xffffffffu, sum, 4);
            if (part == 0) {
                float alpha = __expf(mold - mnew);
                rowa[row] = alpha;
                rowl[row] = rowl[row] * alpha + sum;
                rowm[row] = mnew;
            }
        }

        CP_WAIT1();            // V[t] done (K[t+1] may still be in flight)
        __syncthreads();       // P + rowa visible; V visible

        // ---- rescale O, accumulate O += P @ V
        {
            const int r0 = wm * 16 + (lane >> 2);
            const float a0 = rowa[r0], a1 = rowa[r0 + 8];
            #pragma unroll
            for (int nf = 0; nf < 8; nf++) {
                o[nf][0] *= a0; o[nf][1] *= a0;
                o[nf][2] *= a1; o[nf][3] *= a1;
            }
            #pragma unroll
            for (int ks = 0; ks < 64; ks += 8) {
                const int ac = ks + (lane & 3);
                uint32_t a[4];                      // P fresh -> explicit round
                a[0] = f2tf32(Ss[r0 * SS_STRIDE + ac]);
                a[1] = f2tf32(Ss[(r0 + 8) * SS_STRIDE + ac]);
                a[2] = f2tf32(Ss[r0 * SS_STRIDE + ac + 4]);
                a[3] = f2tf32(Ss[(r0 + 8) * SS_STRIDE + ac + 4]);
                #pragma unroll
                for (int nf = 0; nf < 8; nf++) {
                    int bc = wn * 64 + nf * 8 + (lane >> 2);      // d column
                    uint32_t bb[2];                               // V pre-rounded
                    bb[0] = __float_as_uint(Vs[ac * VS_STRIDE + bc]);
                    bb[1] = __float_as_uint(Vs[(ac + 4) * VS_STRIDE + bc]);
                    mma_tf32(o[nf], a, bb);
                }
            }
        }
        __syncthreads();       // all V reads done

        // ---- prefetch V[t+1] into the (now free) V buffer
        if (kt + 1 < nkt) {
            #pragma unroll
            for (int it = 0; it < 8; it++) {
                int idx = tid + it * 512;
                int r = idx >> 6, c4 = (idx & 63) * 4;
                cp16(&Vs[r * VS_STRIDE + c4],
                     &g_V[base + (size_t)((kt + 1) * 64 + r) * HH + c4]);
            }
        }
        CP_COMMIT();
    }

    // ---- epilogue: O /= l, store
    {
        const int r0 = wm * 16 + (lane >> 2);
        const float inv0 = 1.f / rowl[r0];
        const float inv1 = 1.f / rowl[r0 + 8];
        const size_t orow0 = base + (size_t)(qt * 64 + r0) * HH;
        const size_t orow1 = base + (size_t)(qt * 64 + r0 + 8) * HH;
        #pragma unroll
        for (int nf = 0; nf < 8; nf++) {
            int c0 = wn * 64 + nf * 8 + 2 * (lane & 3);
            out[orow0 + c0]     = o[nf][0] * inv0;
            out[orow0 + c0 + 1] = o[nf][1] * inv0;
            out[orow1 + c0]     = o[nf][2] * inv1;
            out[orow1 + c0 + 1] = o[nf][3] * inv1;
        }
    }
}

// ---------------------------------------------------------------------------
// Launch
// ---------------------------------------------------------------------------
extern "C" void kernel_launch(void* const* d_in, const int* in_sizes, int n_in,
                              void* d_out, int out_size)
{
    const float* x    = (const float*)d_in[0];
    const float* Wq   = (const float*)d_in[1];
    const float* Wk   = (const float*)d_in[2];
    const float* Wv   = (const float*)d_in[3];
    const int*   lens = (const int*)d_in[4];
    float* out = (float*)d_out;
    (void)in_sizes; (void)n_in; (void)out_size;

    cudaFuncSetAttribute(attn_kernel,
                         cudaFuncAttributeMaxDynamicSharedMemorySize,
                         ATTN_SMEM_BYTES);

    dim3 pgrid(M_TOT / 64, HH / 64, 3);
    proj_kernel<<<pgrid, 256>>>(x, Wq, Wk, Wv, lens);

    dim3 agrid(LL / 64, BB);
    attn_kernel<<<agrid, 512, ATTN_SMEM_BYTES>>>(lens, out);
}

// round 5
// speedup vs baseline: 2.0729x; 1.7489x over previous
#include <cuda_runtime.h>
#include <cuda_fp16.h>
#include <cstdint>

#define BB 8
#define LL 2048
#define HH 256
#define M_TOT (BB*LL)

// Scratch (static device globals — allocation-free, graph-capture legal)
__device__ __half g_Q[M_TOT*HH];          // [b*L + q][h], pre-scaled by 1/sqrt(H)
__device__ __half g_K[M_TOT*HH];          // [b*L + k][h]
__device__ __half g_Vt[BB*HH*LL];         // TRANSPOSED: [b][d][kv]

// ---------------------------------------------------------------------------
// Helpers
// ---------------------------------------------------------------------------
__device__ __forceinline__ void mma_f16(float c[4], const uint32_t a[4], const uint32_t b[2]) {
    asm volatile(
        "mma.sync.aligned.m16n8k16.row.col.f32.f16.f16.f32 "
        "{%0,%1,%2,%3}, {%4,%5,%6,%7}, {%8,%9}, {%0,%1,%2,%3};"
        : "+f"(c[0]), "+f"(c[1]), "+f"(c[2]), "+f"(c[3])
        : "r"(a[0]), "r"(a[1]), "r"(a[2]), "r"(a[3]), "r"(b[0]), "r"(b[1]));
}
__device__ __forceinline__ void cp16(__half* s, const __half* g) {
    uint32_t sa = (uint32_t)__cvta_generic_to_shared(s);
    asm volatile("cp.async.cg.shared.global [%0], [%1], 16;" :: "r"(sa), "l"(g));
}
#define CP_COMMIT() asm volatile("cp.async.commit_group;" ::: "memory")
#define CP_WAIT1()  asm volatile("cp.async.wait_group 1;" ::: "memory")
__device__ __forceinline__ uint32_t ldh2(const __half* p) { return *(const uint32_t*)p; }

// ---------------------------------------------------------------------------
// Kernel 1: QKV projection, y = x @ W^T, fp16 mma (m16n8k16), fp32 accum.
// Q output pre-scaled by 1/sqrt(H). V output written TRANSPOSED via smem stage.
// grid (M_TOT/64, HH/64, 3), block 256 (8 warps, 4m x 2n of a 64x64 tile).
// ---------------------------------------------------------------------------
__global__ __launch_bounds__(256, 2)
void proj_kernel(const float* __restrict__ x,
                 const float* __restrict__ Wq,
                 const float* __restrict__ Wk,
                 const float* __restrict__ Wv,
                 const int* __restrict__ lens)
{
    const int mtile = blockIdx.x, ntile = blockIdx.y, which = blockIdx.z;
    const float* Wp = (which == 0) ? Wq : (which == 1) ? Wk : Wv;

    // K/V rows beyond len[b] are never read by attention — skip those tiles.
    if (which != 0) {
        int m0 = mtile * 64;
        int b = m0 / LL, pos = m0 % LL;
        if (pos >= lens[b]) return;
    }

    __shared__ __half Xs[64][72];   // stride 72 halves = 36 words ≡ 4 mod 32
    __shared__ __half Ws[64][72];

    const int tid = threadIdx.x;
    const int lane = tid & 31, warp = tid >> 5;
    const int wm = warp & 3, wn = warp >> 2;   // 4 x 2 warp grid

    float acc[4][4];
    #pragma unroll
    for (int i = 0; i < 4; i++)
        #pragma unroll
        for (int j = 0; j < 4; j++) acc[i][j] = 0.f;

    for (int kc = 0; kc < HH; kc += 64) {
        #pragma unroll
        for (int it = 0; it < 4; it++) {
            int idx = tid + it * 256;          // 1024 float4 per operand
            int r = idx >> 4, c4 = (idx & 15) * 4;
            float4 xv = *(const float4*)&x[(size_t)(mtile * 64 + r) * HH + kc + c4];
            float4 wv = *(const float4*)&Wp[(size_t)(ntile * 64 + r) * HH + kc + c4];
            *(__half2*)&Xs[r][c4]     = __floats2half2_rn(xv.x, xv.y);
            *(__half2*)&Xs[r][c4 + 2] = __floats2half2_rn(xv.z, xv.w);
            *(__half2*)&Ws[r][c4]     = __floats2half2_rn(wv.x, wv.y);
            *(__half2*)&Ws[r][c4 + 2] = __floats2half2_rn(wv.z, wv.w);
        }
        __syncthreads();

        #pragma unroll
        for (int ks = 0; ks < 4; ks++) {       // k-steps of 16
            const int ar = wm * 16 + (lane >> 2);
            const int k0 = ks * 16 + (lane & 3) * 2;
            uint32_t a[4];
            a[0] = ldh2(&Xs[ar][k0]);
            a[1] = ldh2(&Xs[ar + 8][k0]);
            a[2] = ldh2(&Xs[ar][k0 + 8]);
            a[3] = ldh2(&Xs[ar + 8][k0 + 8]);
            #pragma unroll
            for (int nf = 0; nf < 4; nf++) {
                int br = wn * 32 + nf * 8 + (lane >> 2);
                uint32_t b[2];
                b[0] = ldh2(&Ws[br][k0]);
                b[1] = ldh2(&Ws[br][k0 + 8]);
                mma_f16(acc[nf], a, b);
            }
        }
        __syncthreads();
    }

    if (which != 2) {
        // Q/K: store fp16 row-major (Q pre-scaled by 1/sqrt(256) = 2^-4)
        __half* outp = (which == 0) ? g_Q : g_K;
        const float scl = (which == 0) ? 0.0625f : 1.0f;
        const int r0 = mtile * 64 + wm * 16 + (lane >> 2);
        #pragma unroll
        for (int nf = 0; nf < 4; nf++) {
            int c0 = ntile * 64 + wn * 32 + nf * 8 + 2 * (lane & 3);
            *(__half2*)&outp[(size_t)r0 * HH + c0] =
                __floats2half2_rn(acc[nf][0] * scl, acc[nf][1] * scl);
            *(__half2*)&outp[(size_t)(r0 + 8) * HH + c0] =
                __floats2half2_rn(acc[nf][2] * scl, acc[nf][3] * scl);
        }
    } else {
        // V: stage tile in smem (reuse Xs), then write transposed [d][kv]
        const int rl = wm * 16 + (lane >> 2);
        #pragma unroll
        for (int nf = 0; nf < 4; nf++) {
            int cl = wn * 32 + nf * 8 + 2 * (lane & 3);
            *(__half2*)&Xs[rl][cl]     = __floats2half2_rn(acc[nf][0], acc[nf][1]);
            *(__half2*)&Xs[rl + 8][cl] = __floats2half2_rn(acc[nf][2], acc[nf][3]);
        }
        __syncthreads();
        const int d = tid >> 2, part = tid & 3;         // 64 d-rows x 4 parts
        const int m0 = mtile * 64;
        const int b = m0 >> 11, kvb = m0 & 2047;
        __align__(16) __half tmp[16];
        #pragma unroll
        for (int i = 0; i < 16; i++) tmp[i] = Xs[part * 16 + i][d];
        size_t vb = (size_t)b * HH * LL + (size_t)(ntile * 64 + d) * LL + kvb + part * 16;
        *(uint4*)&g_Vt[vb]     = *(uint4*)&tmp[0];
        *(uint4*)&g_Vt[vb + 8] = *(uint4*)&tmp[8];
    }
}

// ---------------------------------------------------------------------------
// Kernel 2: flash attention, fp16 operands, fp32 softmax/accum.
// grid (LL/64, BB), block 512 (16 warps), dyn smem. Same cp.async pipeline as
// R3. Fragments: all contiguous 32-bit LDS (V consumed from transposed tile).
// ---------------------------------------------------------------------------
#define QKS 264   // Q/K row stride (halves): 132 words ≡ 4 mod 32, conflict-free
#define VTS 72    // Vt row stride (halves): 36 words ≡ 4 mod 32
#define SSF 68    // S row stride (floats)
#define PSS 72    // P row stride (halves)

#define OFF_KS  33792
#define OFF_VT  67584
#define OFF_SS  104448
#define OFF_PS  121856
#define OFF_ST  131072
#define ATTN_SMEM_BYTES 131840

__global__ __launch_bounds__(512, 1)
void attn_kernel(const int* __restrict__ lens, float* __restrict__ out)
{
    extern __shared__ unsigned char smr[];
    __half* Qs  = (__half*)smr;
    __half* Ks  = (__half*)(smr + OFF_KS);
    __half* Vts = (__half*)(smr + OFF_VT);
    float*  Ss  = (float*)(smr + OFF_SS);
    __half* Ps  = (__half*)(smr + OFF_PS);
    float*  rowm = (float*)(smr + OFF_ST);
    float*  rowl = rowm + 64;
    float*  rowa = rowl + 64;

    const int qt = blockIdx.x, b = blockIdx.y;
    const int len = lens[b];
    const int tid = threadIdx.x, lane = tid & 31, warp = tid >> 5;
    const int wm = warp & 3, wn = warp >> 2;        // 4 x 4 warp grid
    const size_t kbase = (size_t)b * LL * HH;       // g_Q/g_K row base (halves)
    const size_t vtb   = (size_t)b * HH * LL;       // g_Vt base
    const int nkt = (len + 63) >> 6;

    // Prologue: async-load K0 (group0) and Vt0 (group1)
    #pragma unroll
    for (int it = 0; it < 4; it++) {
        int idx = tid + it * 512;                  // 64 rows x 32 chunks
        int r = idx >> 5, c8 = (idx & 31) * 8;
        cp16(&Ks[r * QKS + c8], &g_K[kbase + (size_t)r * HH + c8]);
    }
    CP_COMMIT();
    #pragma unroll
    for (int it = 0; it < 4; it++) {
        int idx = tid + it * 512;                  // 256 rows x 8 chunks
        int r = idx >> 3, c8 = (idx & 7) * 8;
        cp16(&Vts[r * VTS + c8], &g_Vt[vtb + (size_t)r * LL + c8]);
    }
    CP_COMMIT();

    // Q tile (64 x 256 halves), already pre-scaled in projection
    #pragma unroll
    for (int it = 0; it < 4; it++) {
        int idx = tid + it * 512;
        int r = idx >> 5, c8 = (idx & 31) * 8;
        *(uint4*)&Qs[r * QKS + c8] =
            *(const uint4*)&g_Q[kbase + (size_t)(qt * 64 + r) * HH + c8];
    }
    if (tid < 64) { rowm[tid] = -1e30f; rowl[tid] = 0.f; }

    // O accumulators: warp owns rows [wm*16,+16), cols [wn*64,+64) -> 8 n-frags
    float o[8][4];
    #pragma unroll
    for (int i = 0; i < 8; i++)
        #pragma unroll
        for (int j = 0; j < 4; j++) o[i][j] = 0.f;

    for (int kt = 0; kt < nkt; kt++) {
        CP_WAIT1();            // K[t] done (Vt[t] may still be in flight)
        __syncthreads();

        // ---- S = Q K^T : warp rows [wm*16,+16), cols [wn*16,+16), k-dim 256
        float s[2][4];
        #pragma unroll
        for (int i = 0; i < 2; i++)
            #pragma unroll
            for (int j = 0; j < 4; j++) s[i][j] = 0.f;

        #pragma unroll
        for (int ks = 0; ks < 16; ks++) {          // k-steps of 16
            const int ar = wm * 16 + (lane >> 2);
            const int k0 = ks * 16 + (lane & 3) * 2;
            uint32_t a[4];
            a[0] = ldh2(&Qs[ar * QKS + k0]);
            a[1] = ldh2(&Qs[(ar + 8) * QKS + k0]);
            a[2] = ldh2(&Qs[ar * QKS + k0 + 8]);
            a[3] = ldh2(&Qs[(ar + 8) * QKS + k0 + 8]);
            #pragma unroll
            for (int nf = 0; nf < 2; nf++) {
                int br = wn * 16 + nf * 8 + (lane >> 2);
                uint32_t bb[2];
                bb[0] = ldh2(&Ks[br * QKS + k0]);
                bb[1] = ldh2(&Ks[br * QKS + k0 + 8]);
                mma_f16(s[nf], a, bb);
            }
        }

        // ---- key-padding mask + write S tile (fp32) to smem
        {
            const int r0 = wm * 16 + (lane >> 2);
            #pragma unroll
            for (int nf = 0; nf < 2; nf++) {
                int c0 = wn * 16 + nf * 8 + 2 * (lane & 3);
                int kg = kt * 64 + c0;
                float v0 = (kg     < len) ? s[nf][0] : -1e30f;
                float v1 = (kg + 1 < len) ? s[nf][1] : -1e30f;
                float v2 = (kg     < len) ? s[nf][2] : -1e30f;
                float v3 = (kg + 1 < len) ? s[nf][3] : -1e30f;
                Ss[r0 * SSF + c0]           = v0;
                Ss[r0 * SSF + c0 + 1]       = v1;
                Ss[(r0 + 8) * SSF + c0]     = v2;
                Ss[(r0 + 8) * SSF + c0 + 1] = v3;
            }
        }
        __syncthreads();   // S visible; all K reads done

        // ---- prefetch K[t+1] into the (now free) K buffer
        if (kt + 1 < nkt) {
            #pragma unroll
            for (int it = 0; it < 4; it++) {
                int idx = tid + it * 512;
                int r = idx >> 5, c8 = (idx & 31) * 8;
                cp16(&Ks[r * QKS + c8],
                     &g_K[kbase + (size_t)((kt + 1) * 64 + r) * HH + c8]);
            }
        }
        CP_COMMIT();

        // ---- online softmax: 8 threads per row, 8 cols each; emit P as fp16
        {
            const int row = tid >> 3, part = tid & 7;
            const float* srow = &Ss[row * SSF + part * 8];
            float4 p0 = *(const float4*)&srow[0];
            float4 p1 = *(const float4*)&srow[4];
            float mx = fmaxf(fmaxf(fmaxf(p0.x, p0.y), fmaxf(p0.z, p0.w)),
                             fmaxf(fmaxf(p1.x, p1.y), fmaxf(p1.z, p1.w)));
            mx = fmaxf(mx, __shfl_xor_sync(0xffffffffu, mx, 1));
            mx = fmaxf(mx, __shfl_xor_sync(0xffffffffu, mx, 2));
            mx = fmaxf(mx, __shfl_xor_sync(0xffffffffu, mx, 4));
            const float mold = rowm[row];
            const float mnew = fmaxf(mold, mx);
            p0.x = __expf(p0.x - mnew); p0.y = __expf(p0.y - mnew);
            p0.z = __expf(p0.z - mnew); p0.w = __expf(p0.w - mnew);
            p1.x = __expf(p1.x - mnew); p1.y = __expf(p1.y - mnew);
            p1.z = __expf(p1.z - mnew); p1.w = __expf(p1.w - mnew);
            float sum = (p0.x + p0.y) + (p0.z + p0.w)
                      + (p1.x + p1.y) + (p1.z + p1.w);
            __half2 h0 = __floats2half2_rn(p0.x, p0.y);
            __half2 h1 = __floats2half2_rn(p0.z, p0.w);
            __half2 h2 = __floats2half2_rn(p1.x, p1.y);
            __half2 h3 = __floats2half2_rn(p1.z, p1.w);
            uint4 u;
            u.x = *(uint32_t*)&h0; u.y = *(uint32_t*)&h1;
            u.z = *(uint32_t*)&h2; u.w = *(uint32_t*)&h3;
            *(uint4*)&Ps[row * PSS + part * 8] = u;
            sum += __shfl_xor_sync(0xffffffffu, sum, 1);
            sum += __shfl_xor_sync(0xffffffffu, sum, 2);
            sum += __shfl_xor_sync(0xffffffffu, sum, 4);
            if (part == 0) {
                float alpha = __expf(mold - mnew);
                rowa[row] = alpha;
                rowl[row] = rowl[row] * alpha + sum;
                rowm[row] = mnew;
            }
        }

        CP_WAIT1();            // Vt[t] done (K[t+1] may still be in flight)
        __syncthreads();       // P + rowa visible; Vt visible

        // ---- rescale O, accumulate O += P @ V (from transposed Vt)
        {
            const int r0 = wm * 16 + (lane >> 2);
            const float a0 = rowa[r0], a1 = rowa[r0 + 8];
            #pragma unroll
            for (int nf = 0; nf < 8; nf++) {
                o[nf][0] *= a0; o[nf][1] *= a0;
                o[nf][2] *= a1; o[nf][3] *= a1;
            }
            #pragma unroll
            for (int ks = 0; ks < 4; ks++) {       // 64 kv / 16
                const int k0 = ks * 16 + (lane & 3) * 2;
                uint32_t a[4];
                a[0] = ldh2(&Ps[r0 * PSS + k0]);
                a[1] = ldh2(&Ps[(r0 + 8) * PSS + k0]);
                a[2] = ldh2(&Ps[r0 * PSS + k0 + 8]);
                a[3] = ldh2(&Ps[(r0 + 8) * PSS + k0 + 8]);
                #pragma unroll
                for (int nf = 0; nf < 8; nf++) {
                    int bc = wn * 64 + nf * 8 + (lane >> 2);      // d row of Vt
                    uint32_t bb[2];
                    bb[0] = ldh2(&Vts[bc * VTS + k0]);
                    bb[1] = ldh2(&Vts[bc * VTS + k0 + 8]);
                    mma_f16(o[nf], a, bb);
                }
            }
        }
        __syncthreads();       // all Vt reads done

        // ---- prefetch Vt[t+1] into the (now free) Vt buffer
        if (kt + 1 < nkt) {
            #pragma unroll
            for (int it = 0; it < 4; it++) {
                int idx = tid + it * 512;
                int r = idx >> 3, c8 = (idx & 7) * 8;
                cp16(&Vts[r * VTS + c8],
                     &g_Vt[vtb + (size_t)r * LL + (kt + 1) * 64 + c8]);
            }
        }
        CP_COMMIT();
    }

    // ---- epilogue: O /= l, store
    {
        const int r0 = wm * 16 + (lane >> 2);
        const float inv0 = 1.f / rowl[r0];
        const float inv1 = 1.f / rowl[r0 + 8];
        const size_t base = (size_t)b * LL * HH;
        const size_t orow0 = base + (size_t)(qt * 64 + r0) * HH;
        const size_t orow1 = base + (size_t)(qt * 64 + r0 + 8) * HH;
        #pragma unroll
        for (int nf = 0; nf < 8; nf++) {
            int c0 = wn * 64 + nf * 8 + 2 * (lane & 3);
            out[orow0 + c0]     = o[nf][0] * inv0;
            out[orow0 + c0 + 1] = o[nf][1] * inv0;
            out[orow1 + c0]     = o[nf][2] * inv1;
            out[orow1 + c0 + 1] = o[nf][3] * inv1;
        }
    }
}

// ---------------------------------------------------------------------------
// Launch
// ---------------------------------------------------------------------------
extern "C" void kernel_launch(void* const* d_in, const int* in_sizes, int n_in,
                              void* d_out, int out_size)
{
    const float* x    = (const float*)d_in[0];
    const float* Wq   = (const float*)d_in[1];
    const float* Wk   = (const float*)d_in[2];
    const float* Wv   = (const float*)d_in[3];
    const int*   lens = (const int*)d_in[4];
    float* out = (float*)d_out;
    (void)in_sizes; (void)n_in; (void)out_size;

    cudaFuncSetAttribute(attn_kernel,
                         cudaFuncAttributeMaxDynamicSharedMemorySize,
                         ATTN_SMEM_BYTES);

    dim3 pgrid(M_TOT / 64, HH / 64, 3);
    proj_kernel<<<pgrid, 256>>>(x, Wq, Wk, Wv, lens);

    dim3 agrid(LL / 64, BB);
    attn_kernel<<<agrid, 512, ATTN_SMEM_BYTES>>>(lens, out);
}